// round 4
// baseline (speedup 1.0000x reference)
#include <cuda_runtime.h>
#include <cstdint>

// NonLocalMeansSmoothing: x [8,256,256,8] fp32 -> same. K=5, sigma=1, h=1.
// w ∝ exp(-(||c-n||^2 + 0.5*(di^2+dj^2)))   (gaussian global norm cancels)
// ||c-n||^2 = ||c||^2 + ||n||^2 - 2 c·n, norms pre-scaled by -log2e in smem.
// 2x2 pixels per thread: 36 site-loads serve 100 taps; LDS swizzle kills
// the stride-2 bank conflicts; packed f32x2 math throughout.

#define BATCH 8
#define NX 256
#define NY 256
#define TILE 32
#define HALO 2
#define SMW (TILE + 2 * HALO)   // 36
#define L2E 1.4426950408889634f

typedef unsigned long long u64;

__device__ __forceinline__ u64 fma2(u64 a, u64 b, u64 c) {
    u64 d; asm("fma.rn.f32x2 %0,%1,%2,%3;" : "=l"(d) : "l"(a), "l"(b), "l"(c)); return d;
}
__device__ __forceinline__ u64 mul2(u64 a, u64 b) {
    u64 d; asm("mul.rn.f32x2 %0,%1,%2;" : "=l"(d) : "l"(a), "l"(b)); return d;
}
__device__ __forceinline__ u64 pack2(float lo, float hi) {
    u64 d; asm("mov.b64 %0,{%1,%2};" : "=l"(d) : "f"(lo), "f"(hi)); return d;
}
__device__ __forceinline__ float hadd2(u64 a) {
    float lo, hi; asm("mov.b64 {%0,%1},%2;" : "=f"(lo), "=f"(hi) : "l"(a));
    return lo + hi;
}
__device__ __forceinline__ float ex2f(float x) {
    float r; asm("ex2.approx.ftz.f32 %0,%1;" : "=f"(r) : "f"(x)); return r;
}
__device__ __forceinline__ int refl(int p, int n) {
    if (p < 0) p = -p;
    if (p >= n) p = 2 * n - 2 - p;
    return p;
}
// De-conflict swizzle for 16B-chunk index: any 8-lane stride-2 sequence maps
// to 8 distinct bank-groups.
__device__ __forceinline__ int sw(int k) { return k ^ ((k >> 3) & 1); }

__global__ __launch_bounds__(256, 2)
void nlm_kernel(const float* __restrict__ x, float* __restrict__ out) {
    __shared__ ulonglong2 A0[SMW * SMW];   // ch 0-3, swizzled chunk index
    __shared__ ulonglong2 A1[SMW * SMW];   // ch 4-7, swizzled chunk index
    __shared__ float      SNL[SMW * SMW];  // -log2e * ||v||^2, linear index

    const int b   = blockIdx.z;
    const int ti0 = blockIdx.y * TILE;
    const int tj0 = blockIdx.x * TILE;
    const int tid = threadIdx.y * 16 + threadIdx.x;

    const float* xb = x + (size_t)b * NX * NY * 8;

    // Halo load: 1296 pixels / 256 threads.
    for (int p = tid; p < SMW * SMW; p += 256) {
        int r = p / SMW;
        int c = p - r * SMW;
        int gi = refl(ti0 + r - HALO, NX);
        int gj = refl(tj0 + c - HALO, NY);
        const float4* src = reinterpret_cast<const float4*>(
            xb + ((size_t)gi * NY + gj) * 8);
        float4 v0 = src[0];
        float4 v1 = src[1];
        int ks = sw(p);
        *reinterpret_cast<float4*>(&A0[ks]) = v0;
        *reinterpret_cast<float4*>(&A1[ks]) = v1;
        float nrm = v0.x * v0.x + v0.y * v0.y + v0.z * v0.z + v0.w * v0.w
                  + v1.x * v1.x + v1.y * v1.y + v1.z * v1.z + v1.w * v1.w;
        SNL[p] = -L2E * nrm;
    }
    __syncthreads();

    // Quad: pixels (y0+a, x0+b), a,b in {0,1}; site block rows y0..y0+5, cols x0..x0+5
    const int y0 = 2 * threadIdx.y;   // tile-local row of pixel (0,*) minus halo == smem row base
    const int x0 = 2 * threadIdx.x;

    // Center pixels: smem (y0+2+a, x0+2+b)
    u64 C[4][4];    // [pixel a*2+b][plane pair]: {A0.x, A0.y, A1.x, A1.y}
    float pc[4];
#pragma unroll
    for (int a = 0; a < 2; a++)
#pragma unroll
        for (int bb = 0; bb < 2; bb++) {
            int k = (y0 + 2 + a) * SMW + (x0 + 2 + bb);
            int ks = sw(k);
            ulonglong2 v0 = A0[ks];
            ulonglong2 v1 = A1[ks];
            C[a * 2 + bb][0] = v0.x; C[a * 2 + bb][1] = v0.y;
            C[a * 2 + bb][2] = v1.x; C[a * 2 + bb][3] = v1.y;
            pc[a * 2 + bb] = SNL[k];
        }

    u64 acc[4][4];
#pragma unroll
    for (int p = 0; p < 4; p++)
#pragma unroll
        for (int q = 0; q < 4; q++) acc[p][q] = 0;
    float wsum[4] = {0.f, 0.f, 0.f, 0.f};

#pragma unroll
    for (int r = 0; r < 6; r++) {
#pragma unroll
        for (int c = 0; c < 6; c++) {
            const int k = (y0 + r) * SMW + (x0 + c);
            const int ks = sw(k);
            const ulonglong2 N0 = A0[ks];
            const ulonglong2 N1 = A1[ks];
            const float ns = SNL[k];

#pragma unroll
            for (int a = 0; a < 2; a++) {
                if ((a == 0 && r > 4) || (a == 1 && r < 1)) continue;
#pragma unroll
                for (int bb = 0; bb < 2; bb++) {
                    if ((bb == 0 && c > 4) || (bb == 1 && c < 1)) continue;
                    const int p = a * 2 + bb;
                    const int di = r - a - 2;
                    const int dj = c - bb - 2;
                    const float cg = -L2E * (0.5f * (float)(di * di + dj * dj));

                    u64 dp = mul2(C[p][0], N0.x);
                    dp = fma2(C[p][1], N0.y, dp);
                    dp = fma2(C[p][2], N1.x, dp);
                    dp = fma2(C[p][3], N1.y, dp);
                    const float e = fmaf(2.0f * L2E, hadd2(dp),
                                         pc[p] + (ns + cg));
                    const float w = ex2f(e);
                    const u64 w2 = pack2(w, w);
                    acc[p][0] = fma2(w2, N0.x, acc[p][0]);
                    acc[p][1] = fma2(w2, N0.y, acc[p][1]);
                    acc[p][2] = fma2(w2, N1.x, acc[p][2]);
                    acc[p][3] = fma2(w2, N1.y, acc[p][3]);
                    wsum[p] += w;
                }
            }
        }
    }

#pragma unroll
    for (int a = 0; a < 2; a++)
#pragma unroll
        for (int bb = 0; bb < 2; bb++) {
            const int p = a * 2 + bb;
            const float inv = __fdividef(1.f, wsum[p]);
            const u64 inv2 = pack2(inv, inv);
            ulonglong2 r0, r1;
            r0.x = mul2(acc[p][0], inv2); r0.y = mul2(acc[p][1], inv2);
            r1.x = mul2(acc[p][2], inv2); r1.y = mul2(acc[p][3], inv2);
            const int gi = ti0 + y0 + a;
            const int gj = tj0 + x0 + bb;
            ulonglong2* dst = reinterpret_cast<ulonglong2*>(
                out + (((size_t)b * NX + gi) * NY + gj) * 8);
            dst[0] = r0; dst[1] = r1;
        }
}

extern "C" void kernel_launch(void* const* d_in, const int* in_sizes, int n_in,
                              void* d_out, int out_size) {
    const float* x = (const float*)d_in[0];
    float* out = (float*)d_out;
    dim3 block(16, 16, 1);
    dim3 grid(NY / TILE, NX / TILE, BATCH);  // (8, 8, 8)
    nlm_kernel<<<grid, block>>>(x, out);
}